// round 14
// baseline (speedup 1.0000x reference)
#include <cuda_runtime.h>
#include <cuda_fp16.h>
#include <cstdint>

// Problem constants
constexpr int B  = 2;
constexpr int T  = 2048;
constexpr int D  = 512;
constexpr int H  = 8;
constexpr int DK = 64;         // D / H
constexpr int L  = 2 * T - 1;  // 4095

// ---------------------------------------------------------------------------
// Scratch (no cudaMalloc allowed) — device globals
// ---------------------------------------------------------------------------
__device__ __align__(16) __half g_xq[(size_t)B * T * D];   // fp16 inputs
__device__ __align__(16) __half g_xk[(size_t)B * T * D];
__device__ __align__(16) __half g_xv[(size_t)B * T * D];
__device__ __align__(16) __half g_xp[(size_t)L * D];
__device__ __align__(16) __half g_wq[(size_t)D * D];       // fp16 weights
__device__ __align__(16) __half g_wk[(size_t)D * D];
__device__ __align__(16) __half g_wv[(size_t)D * D];
__device__ __align__(16) __half g_wp[(size_t)D * D];
__device__ __align__(16) __half g_wo[(size_t)D * D];
__device__ __align__(16) __half g_qh[(size_t)B * T * D];   // projected heads
__device__ __align__(16) __half g_kh[(size_t)B * T * D];
__device__ __align__(16) __half g_ph[(size_t)L * D];
__device__ __align__(16) __half g_vht[(size_t)B * H * DK * T];  // V^T per head
__device__ __align__(16) __half g_aoh[(size_t)B * T * D];  // attention out (fp16)

// ---------------------------------------------------------------------------
// Helpers
// ---------------------------------------------------------------------------
__device__ __forceinline__ void mma_f16(float c[4], const uint32_t a[4],
                                        uint32_t b0, uint32_t b1) {
    asm volatile(
        "mma.sync.aligned.m16n8k16.row.col.f32.f16.f16.f32 "
        "{%0,%1,%2,%3}, {%4,%5,%6,%7}, {%8,%9}, {%0,%1,%2,%3};"
        : "+f"(c[0]), "+f"(c[1]), "+f"(c[2]), "+f"(c[3])
        : "r"(a[0]), "r"(a[1]), "r"(a[2]), "r"(a[3]), "r"(b0), "r"(b1));
}

__device__ __forceinline__ void ldsm_x4(uint32_t r[4], uint32_t addr) {
    asm volatile(
        "ldmatrix.sync.aligned.m8n8.x4.shared.b16 {%0,%1,%2,%3}, [%4];"
        : "=r"(r[0]), "=r"(r[1]), "=r"(r[2]), "=r"(r[3]) : "r"(addr));
}

__device__ __forceinline__ uint32_t h2u(__half2 h) {
    return *reinterpret_cast<uint32_t*>(&h);
}

__device__ __forceinline__ float fast_exp2(float x) {
    float r;
    asm("ex2.approx.f32 %0, %1;" : "=f"(r) : "f"(x));
    return r;
}

__device__ __forceinline__ uint32_t s2u(const void* p) {
    return (uint32_t)__cvta_generic_to_shared(p);
}
__device__ __forceinline__ void cp16(uint32_t dst, const void* src) {
    asm volatile("cp.async.ca.shared.global [%0], [%1], 16;" :: "r"(dst), "l"(src));
}
__device__ __forceinline__ void cp_commit() { asm volatile("cp.async.commit_group;"); }
__device__ __forceinline__ void cp_wait0()  { asm volatile("cp.async.wait_group 0;"); }

// ---------------------------------------------------------------------------
// Fused fp32 -> fp16 converter: one launch, 9 segments on blockIdx.y
// ---------------------------------------------------------------------------
__global__ __launch_bounds__(256)
void f2h_all_kernel(const float4* __restrict__ q, const float4* __restrict__ k,
                    const float4* __restrict__ v, const float4* __restrict__ p,
                    const float4* __restrict__ Wq, const float4* __restrict__ Wk,
                    const float4* __restrict__ Wv, const float4* __restrict__ Wp,
                    const float4* __restrict__ Wo) {
    const int seg = blockIdx.y;
    const int nTD4 = B * T * D / 4, nLD4 = L * D / 4, nDD4 = D * D / 4;
    const float4* s;
    uint2* d;
    int n4;
    switch (seg) {
        case 0: s = q;  d = (uint2*)g_xq; n4 = nTD4; break;
        case 1: s = k;  d = (uint2*)g_xk; n4 = nTD4; break;
        case 2: s = v;  d = (uint2*)g_xv; n4 = nTD4; break;
        case 3: s = p;  d = (uint2*)g_xp; n4 = nLD4; break;
        case 4: s = Wq; d = (uint2*)g_wq; n4 = nDD4; break;
        case 5: s = Wk; d = (uint2*)g_wk; n4 = nDD4; break;
        case 6: s = Wv; d = (uint2*)g_wv; n4 = nDD4; break;
        case 7: s = Wp; d = (uint2*)g_wp; n4 = nDD4; break;
        default: s = Wo; d = (uint2*)g_wo; n4 = nDD4; break;
    }
    for (int i = blockIdx.x * blockDim.x + threadIdx.x; i < n4;
         i += gridDim.x * blockDim.x) {
        float4 x = s[i];
        uint2 o;
        o.x = h2u(__floats2half2_rn(x.x, x.y));
        o.y = h2u(__floats2half2_rn(x.z, x.w));
        d[i] = o;
    }
}

// ---------------------------------------------------------------------------
// FP16 GEMM body: Y[M,512] = X[M,512] @ W[512,512]^T + bias
// 128x128 block tile, BK=64, 256 threads, cp.async double buffered, 2 CTA/SM.
// OUT_F32: fp32 output.  VT: write transposed per-head V^T to g_vht instead.
// ---------------------------------------------------------------------------
constexpr int HW = 72;                   // half row stride
constexpr int PBUF = 128 * HW;           // halves per tile buffer
constexpr size_t PROJ_SMEM_BYTES = (size_t)4 * PBUF * sizeof(__half);  // 73728
constexpr int TST = 136;                 // transpose-stage row stride (halves)

template <bool OUT_F32, bool VT>
__device__ __forceinline__ void fp16_gemm_body(const __half* __restrict__ X,
                                               const __half* __restrict__ W,
                                               const float* __restrict__ bias,
                                               void* __restrict__ Yv, int M,
                                               __half* hsm) {
    __half* Xs = hsm;                // 2 buffers
    __half* Ws = hsm + 2 * PBUF;     // 2 buffers

    const int tid = threadIdx.x;
    const int lane = tid & 31, wid = tid >> 5;
    const int wm = wid & 1, wn = wid >> 1;      // 2x4 warps, warp tile 64x32
    const int m0w = wm * 64, n0w = wn * 32;
    const int lr = lane >> 2, lc = lane & 3;
    const int m0 = blockIdx.y * 128, n0 = blockIdx.x * 128;

    const int a_ofs = (m0w + (lane & 15)) * HW + ((lane >> 4) << 3);
    const int b_ofs = (n0w + (lane & 7) + ((lane >> 4) << 3)) * HW
                      + (((lane >> 3) & 1) << 3);

    auto issue = [&](int t, int buf) {
        const int k0 = t * 64;
        __half* Xd = Xs + buf * PBUF;
        __half* Wd = Ws + buf * PBUF;
#pragma unroll
        for (int it = 0; it < 4; it++) {
            int i = tid + it * 256;
            int r = i >> 3, c8 = (i & 7) * 8;
            int gr = m0 + r;
            __half* xd = &Xd[r * HW + c8];
            if (gr < M) cp16(s2u(xd), &X[(size_t)gr * D + k0 + c8]);
            else        *(float4*)xd = make_float4(0.f, 0.f, 0.f, 0.f);
            cp16(s2u(&Wd[r * HW + c8]), &W[(size_t)(n0 + r) * D + k0 + c8]);
        }
    };

    float acc[4][4][4] = {};

    issue(0, 0);
    cp_commit();

    for (int t = 0; t < 8; t++) {
        cp_wait0();
        __syncthreads();
        if (t + 1 < 8) issue(t + 1, (t + 1) & 1);
        cp_commit();

        const __half* Xb = Xs + (t & 1) * PBUF;
        const __half* Wb = Ws + (t & 1) * PBUF;
#pragma unroll
        for (int ks = 0; ks < 4; ks++) {
            const int kk = ks * 16;
            uint32_t a[4][4];
#pragma unroll
            for (int mf = 0; mf < 4; mf++)
                ldsm_x4(a[mf], s2u(Xb + a_ofs + mf * 16 * HW + kk));
#pragma unroll
            for (int nfp = 0; nfp < 2; nfp++) {
                uint32_t bw[4];
                ldsm_x4(bw, s2u(Wb + b_ofs + nfp * 16 * HW + kk));
#pragma unroll
                for (int mf = 0; mf < 4; mf++) {
                    mma_f16(acc[mf][2 * nfp],     a[mf], bw[0], bw[1]);
                    mma_f16(acc[mf][2 * nfp + 1], a[mf], bw[2], bw[3]);
                }
            }
        }
        __syncthreads();
    }

    if (VT) {
        // Stage 128x128 tile transposed in smem: ts[c_local][t_local]
        __half* ts = hsm;
#pragma unroll
        for (int mf = 0; mf < 4; mf++) {
#pragma unroll
            for (int hf = 0; hf < 2; hf++) {
                const int rl = m0w + mf * 16 + hf * 8 + lr;
#pragma unroll
                for (int nf = 0; nf < 4; nf++) {
                    const int cl = n0w + nf * 8 + 2 * lc;
                    ts[cl * TST + rl] =
                        __float2half_rn(acc[mf][nf][hf * 2] + bias[n0 + cl]);
                    ts[(cl + 1) * TST + rl] =
                        __float2half_rn(acc[mf][nf][hf * 2 + 1] + bias[n0 + cl + 1]);
                }
            }
        }
        __syncthreads();
        // Coalesced write-out: g_vht[(b*8+h)*64 + d][t]
        const int b_ = m0 / T, t0_ = m0 % T;
        for (int idx = tid; idx < 128 * 16; idx += 256) {
            const int cl = idx >> 4, t8 = (idx & 15) * 8;
            const int c = n0 + cl;
            const int h_ = c >> 6, d_ = c & 63;
            uint4 vdat = *(const uint4*)&ts[cl * TST + t8];
            *(uint4*)&g_vht[((size_t)(b_ * 8 + h_) * 64 + d_) * T + t0_ + t8] = vdat;
        }
        return;
    }

#pragma unroll
    for (int mf = 0; mf < 4; mf++) {
#pragma unroll
        for (int hf = 0; hf < 2; hf++) {
            const int r = m0 + m0w + mf * 16 + hf * 8 + lr;
            if (r >= M) continue;
#pragma unroll
            for (int nf = 0; nf < 4; nf++) {
                const int c = n0 + n0w + nf * 8 + 2 * lc;
                float b0 = bias ? bias[c] : 0.f;
                float b1 = bias ? bias[c + 1] : 0.f;
                float vx = acc[mf][nf][hf * 2] + b0;
                float vy = acc[mf][nf][hf * 2 + 1] + b1;
                if (OUT_F32) {
                    float* Y = (float*)Yv;
                    *(float2*)&Y[(size_t)r * D + c] = make_float2(vx, vy);
                } else {
                    __half* Y = (__half*)Yv;
                    *(__half2*)&Y[(size_t)r * D + c] = __floats2half2_rn(vx, vy);
                }
            }
        }
    }
}

__global__ __launch_bounds__(256, 2)
void proj_fp16_kernel(const float* __restrict__ bq, const float* __restrict__ bk,
                      const float* __restrict__ bv) {
    extern __shared__ __align__(16) __half hsm[];
    const int z = blockIdx.z;
    if (z == 2) {
        // V projection: write transposed per-head layout directly
        fp16_gemm_body<false, true>(g_xv, g_wv, bv, nullptr, B * T, hsm);
        return;
    }
    const __half* X = (z == 0) ? g_xq : (z == 1) ? g_xk : g_xp;
    const __half* W = (z == 0) ? g_wq : (z == 1) ? g_wk : g_wp;
    const float* bias = (z == 0) ? bq : (z == 1) ? bk : nullptr;
    __half* Y = (z == 0) ? g_qh : (z == 1) ? g_kh : g_ph;
    const int M = (z == 3) ? L : B * T;
    fp16_gemm_body<false, false>(X, W, bias, Y, M, hsm);
}

__global__ __launch_bounds__(256, 2)
void out_gemm_fp16_kernel(const float* __restrict__ bo, float* __restrict__ Y) {
    extern __shared__ __align__(16) __half hsm[];
    fp16_gemm_body<true, false>(g_aoh, g_wo, bo, Y, B * T, hsm);
}

// ---------------------------------------------------------------------------
// Rel-pos flash attention: uniform lag-1 pipeline, 2 barriers per k-tile.
//  Iter kt phase (a): PV(kt-1) + AC(kt) + BD(kt+1) mma burst, ring write.
//  barrier.  phase (b): softmax(kt) -> Ph[kt&1].  cp_wait + barrier.
//  Buffers: K x2, V x3, P x2, Ph x2, ring 2 slots (+4 dup).
//  Softmax scale pre-folded into Q fragments; softmax is exp2(a+b).
// ---------------------------------------------------------------------------
constexpr int HP  = 72;
constexpr int RST = 132;
constexpr int TILE_H = 64 * HP;         // halves per tile
constexpr int TILE_HB = TILE_H * 2;     // 9216 bytes

constexpr int OFF_K  = 0;                        // 2 buffers
constexpr int OFF_VT = OFF_K  + 2 * TILE_HB;     // 3 buffers
constexpr int OFF_P  = OFF_VT + 3 * TILE_HB;     // 2 buffers
constexpr int OFF_PH = OFF_P  + 2 * TILE_HB;     // 2 buffers (Q stage / probs)
constexpr int OFF_BD = OFF_PH + 2 * TILE_HB;     // 64 x 132 half ring
constexpr int OFF_LS = OFF_BD + 64 * RST * 2;    // 128 floats
constexpr int ATT_BYTES = OFF_LS + 128 * 4;      // 100864 bytes

__global__ __launch_bounds__(256, 2)
void attn_fp16_kernel(const float* __restrict__ bu, const float* __restrict__ bvb) {
    extern __shared__ __align__(16) char smx[];
    __half* Ks  = (__half*)(smx + OFF_K);
    __half* Vts = (__half*)(smx + OFF_VT);
    __half* Ps  = (__half*)(smx + OFF_P);
    __half* Ph  = (__half*)(smx + OFF_PH);
    __half* BDh = (__half*)(smx + OFF_BD);
    float*  LS  = (float*) (smx + OFF_LS);

    const int tid = threadIdx.x;
    const int lane = tid & 31, wid = tid >> 5;
    const int wm = wid & 3, wn = wid >> 2;          // 4x2 warp grid
    const int m0w = wm * 16, n0w = wn * 32;         // warp tile 16x32
    const int lr = lane >> 2, lc = lane & 3;

    const int a_ofs = (m0w + (lane & 15)) * HP + ((lane >> 4) << 3);
    const int b_ofs = (n0w + (lane & 7) + ((lane >> 4) << 3)) * HP
                      + (((lane >> 3) & 1) << 3);

    const int q0 = blockIdx.x * 64;
    const int bh = blockIdx.y;
    const int b = bh >> 3, h = bh & 7;
    const int base_p = T - 1 - q0 - 63;   // >= 0

    const __half* qb = g_qh + (size_t)b * T * D + h * DK;
    const __half* kb = g_kh + (size_t)b * T * D + h * DK;
    const __half* vtb = g_vht + (size_t)bh * DK * T;
    const __half* pb = g_ph + h * DK;

    auto issue_k = [&](int kt) {
        const __half* kbase = kb + (size_t)(kt * 64) * D;
        __half* Kd = Ks + (kt & 1) * TILE_H;
#pragma unroll
        for (int it = 0; it < 2; it++) {
            int i = tid + it * 256;
            int r = i >> 3, c8 = (i & 7) * 8;
            cp16(s2u(&Kd[r * HP + c8]), kbase + (size_t)r * D + c8);
        }
    };
    auto issue_v = [&](int kt) {
        const __half* vbase = vtb + kt * 64;
        __half* Vd = Vts + (kt % 3) * TILE_H;
#pragma unroll
        for (int it = 0; it < 2; it++) {
            int i = tid + it * 256;
            int r = i >> 3, c8 = (i & 7) * 8;
            cp16(s2u(&Vd[r * HP + c8]), vbase + (size_t)r * T + c8);
        }
    };
    auto issue_p = [&](int ch) {
        __half* Pd = Ps + (ch & 1) * TILE_H;
#pragma unroll
        for (int it = 0; it < 2; it++) {
            int i = tid + it * 256;
            int r = i >> 3, c8 = (i & 7) * 8;
            int g = base_p + ch * 64 + r;
            __half* dst = &Pd[r * HP + c8];
            if (g < L) cp16(s2u(dst), pb + (size_t)g * D + c8);
            else       *(float4*)dst = make_float4(0.f, 0.f, 0.f, 0.f);
        }
    };

    // ---- stage Q into Ph[0], build register A-fragments with bias+scale ----
#pragma unroll
    for (int it = 0; it < 2; it++) {
        int i = tid + it * 256;
        int r = i >> 3, c8 = (i & 7) * 8;
        cp16(s2u(&Ph[r * HP + c8]), qb + (size_t)(q0 + r) * D + c8);
    }
    cp_commit();
    cp_wait0();
    __syncthreads();

    constexpr float SCQ = 0.125f * 1.4426950408889634f;  // 1/sqrt(64) * log2(e)
    const int rA = m0w + lr, rB = rA + 8;
    uint32_t qf1[4][4], qf2[4][4];
#pragma unroll
    for (int ks = 0; ks < 4; ks++) {
        const int cc = ks * 16 + 2 * lc;
        float2 buL = *(const float2*)&bu[h * DK + cc];
        float2 buH = *(const float2*)&bu[h * DK + cc + 8];
        float2 bvL = *(const float2*)&bvb[h * DK + cc];
        float2 bvH = *(const float2*)&bvb[h * DK + cc + 8];
        float2 qaL = __half22float2(*(const __half2*)&Ph[rA * HP + cc]);
        float2 qbL = __half22float2(*(const __half2*)&Ph[rB * HP + cc]);
        float2 qaH = __half22float2(*(const __half2*)&Ph[rA * HP + cc + 8]);
        float2 qbH = __half22float2(*(const __half2*)&Ph[rB * HP + cc + 8]);
        qf1[ks][0] = h2u(__floats2half2_rn((qaL.x + buL.x) * SCQ, (qaL.y + buL.y) * SCQ));
        qf1[ks][1] = h2u(__floats2half2_rn((qbL.x + buL.x) * SCQ, (qbL.y + buL.y) * SCQ));
        qf1[ks][2] = h2u(__floats2half2_rn((qaH.x + buH.x) * SCQ, (qaH.y + buH.y) * SCQ));
        qf1[ks][3] = h2u(__floats2half2_rn((qbH.x + buH.x) * SCQ, (qbH.y + buH.y) * SCQ));
        qf2[ks][0] = h2u(__floats2half2_rn((qaL.x + bvL.x) * SCQ, (qaL.y + bvL.y) * SCQ));
        qf2[ks][1] = h2u(__floats2half2_rn((qbL.x + bvL.x) * SCQ, (qbL.y + bvL.y) * SCQ));
        qf2[ks][2] = h2u(__floats2half2_rn((qaH.x + bvH.x) * SCQ, (qaH.y + bvH.y) * SCQ));
        qf2[ks][3] = h2u(__floats2half2_rn((qbH.x + bvH.x) * SCQ, (qbH.y + bvH.y) * SCQ));
    }
    __syncthreads();   // Ph[0] free for probs

    issue_k(0);
    issue_v(0);
    issue_p(0);
    issue_p(1);
    cp_commit();
    cp_wait0();
    __syncthreads();

    // ---- prologue: BD chunk 0 -> ring slot 0 ----
    {
        const __half* Pb = Ps;  // chunk 0, buf 0
        float accB[4][4] = {};
#pragma unroll
        for (int ks = 0; ks < 4; ks++) {
            const int kk = ks * 16;
#pragma unroll
            for (int nfp = 0; nfp < 2; nfp++) {
                uint32_t bp_[4];
                ldsm_x4(bp_, s2u(Pb + b_ofs + nfp * 16 * HP + kk));
                mma_f16(accB[2 * nfp],     qf2[ks], bp_[0], bp_[1]);
                mma_f16(accB[2 * nfp + 1], qf2[ks], bp_[2], bp_[3]);
            }
        }
#pragma unroll
        for (int nf = 0; nf < 4; nf++) {
            const int cr = n0w + nf * 8 + 2 * lc;
            uint32_t lo = h2u(__floats2half2_rn(accB[nf][0], accB[nf][1]));
            uint32_t hi = h2u(__floats2half2_rn(accB[nf][2], accB[nf][3]));
            *(uint32_t*)&BDh[rA * RST + cr] = lo;
            *(uint32_t*)&BDh[rB * RST + cr] = hi;
            if (cr < 4) {
                *(uint32_t*)&BDh[rA * RST + cr + 128] = lo;
                *(uint32_t*)&BDh[rB * RST + cr + 128] = hi;
            }
        }
    }
    __syncthreads();

    float O[4][4] = {};
    float lsumA = 0.f, lsumB = 0.f;

    for (int kt = 0; kt < 32; kt++) {
        // ---- phase (a): prefetch + mma burst (PV(kt-1), AC(kt), BD(kt+1)) ----
        if (kt + 1 < 32) { issue_k(kt + 1); issue_v(kt + 1); }
        if (kt + 2 <= 32) issue_p(kt + 2);
        cp_commit();

        // PV(kt-1): Ph[(kt-1)&1] and Vts[(kt-1)%3] stable since last barrier
        if (kt > 0) {
            const __half* Phb = Ph + ((kt - 1) & 1) * TILE_H;
            const __half* Vb  = Vts + ((kt - 1) % 3) * TILE_H;
#pragma unroll
            for (int ks = 0; ks < 4; ks++) {
                const int kk = ks * 16;
                uint32_t a[4];
                ldsm_x4(a, s2u(Phb + a_ofs + kk));
#pragma unroll
                for (int nfp = 0; nfp < 2; nfp++) {
                    uint32_t bv_[4];
                    ldsm_x4(bv_, s2u(Vb + b_ofs + nfp * 16 * HP + kk));
                    mma_f16(O[2 * nfp],     a, bv_[0], bv_[1]);
                    mma_f16(O[2 * nfp + 1], a, bv_[2], bv_[3]);
                }
            }
        }

        // AC(kt) -> regs ; BD(kt+1) -> ring slot (kt+1)&1
        const __half* Kb = Ks + (kt & 1) * TILE_H;
        const __half* Pb = Ps + ((kt + 1) & 1) * TILE_H;
        float accA[4][4] = {};
        {
            float accB[4][4] = {};
#pragma unroll
            for (int ks = 0; ks < 4; ks++) {
                const int kk = ks * 16;
#pragma unroll
                for (int nfp = 0; nfp < 2; nfp++) {
                    uint32_t bk_[4], bp_[4];
                    ldsm_x4(bk_, s2u(Kb + b_ofs + nfp * 16 * HP + kk));
                    mma_f16(accA[2 * nfp],     qf1[ks], bk_[0], bk_[1]);
                    mma_f16(accA[2 * nfp + 1], qf1[ks], bk_[2], bk_[3]);
                    ldsm_x4(bp_, s2u(Pb + b_ofs + nfp * 16 * HP + kk));
                    mma_f16(accB[2 * nfp],     qf2[ks], bp_[0], bp_[1]);
                    mma_f16(accB[2 * nfp + 1], qf2[ks], bp_[2], bp_[3]);
                }
            }
            const int slotc = ((kt + 1) & 1) * 64;
#pragma unroll
            for (int nf = 0; nf < 4; nf++) {
                const int cr = slotc + n0w + nf * 8 + 2 * lc;
                uint32_t lo = h2u(__floats2half2_rn(accB[nf][0], accB[nf][1]));
                uint32_t hi = h2u(__floats2half2_rn(accB[nf][2], accB[nf][3]));
                *(uint32_t*)&BDh[rA * RST + cr] = lo;
                *(uint32_t*)&BDh[rB * RST + cr] = hi;
                if (cr < 4) {
                    *(uint32_t*)&BDh[rA * RST + cr + 128] = lo;
                    *(uint32_t*)&BDh[rB * RST + cr + 128] = hi;
                }
            }
        }
        __syncthreads();   // barrier1: ring complete, PV(kt-1) reads done

        // ---- phase (b): fragment softmax(kt) -> Ph[kt&1] ----
        {
            __half* Phb = Ph + (kt & 1) * TILE_H;
            const int base_w = 63 + 64 * kt;
#pragma unroll
            for (int nf = 0; nf < 4; nf++) {
                const int c = n0w + nf * 8 + 2 * lc;
                const int wbA = (base_w - rA + c) & 127;
                const int wbB = (base_w - rB + c) & 127;
                float p0 = fast_exp2(accA[nf][0] + __half2float(BDh[rA * RST + wbA]));
                float p1 = fast_exp2(accA[nf][1] + __half2float(BDh[rA * RST + wbA + 1]));
                float p2 = fast_exp2(accA[nf][2] + __half2float(BDh[rB * RST + wbB]));
                float p3 = fast_exp2(accA[nf][3] + __half2float(BDh[rB * RST + wbB + 1]));
                lsumA += p0 + p1;
                lsumB += p2 + p3;
                *(uint32_t*)&Phb[rA * HP + c] = h2u(__floats2half2_rn(p0, p1));
                *(uint32_t*)&Phb[rB * HP + c] = h2u(__floats2half2_rn(p2, p3));
            }
        }
        cp_wait0();
        __syncthreads();   // barrier2: probs visible, cp buffers ready
    }

    // ---- epilogue: PV(31) ----
    {
        const __half* Phb = Ph + (31 & 1) * TILE_H;
        const __half* Vb  = Vts + (31 % 3) * TILE_H;
#pragma unroll
        for (int ks = 0; ks < 4; ks++) {
            const int kk = ks * 16;
            uint32_t a[4];
            ldsm_x4(a, s2u(Phb + a_ofs + kk));
#pragma unroll
            for (int nfp = 0; nfp < 2; nfp++) {
                uint32_t bv_[4];
                ldsm_x4(bv_, s2u(Vb + b_ofs + nfp * 16 * HP + kk));
                mma_f16(O[2 * nfp],     a, bv_[0], bv_[1]);
                mma_f16(O[2 * nfp + 1], a, bv_[2], bv_[3]);
            }
        }
    }

    // ---- final row-sum: quad shfl + 2-warp smem combine ----
    lsumA += __shfl_xor_sync(0xffffffffu, lsumA, 1);
    lsumA += __shfl_xor_sync(0xffffffffu, lsumA, 2);
    lsumB += __shfl_xor_sync(0xffffffffu, lsumB, 1);
    lsumB += __shfl_xor_sync(0xffffffffu, lsumB, 2);
    if (lc == 0) {
        LS[wn * 64 + rA] = lsumA;
        LS[wn * 64 + rB] = lsumB;
    }
    __syncthreads();

    {
        const float inv0 = 1.f / (LS[rA] + LS[64 + rA]);
        const float inv1 = 1.f / (LS[rB] + LS[64 + rB]);
        const size_t row0 = (size_t)(b * T + q0 + rA) * D + h * DK;
        const size_t row1 = row0 + (size_t)8 * D;
#pragma unroll
        for (int nf = 0; nf < 4; nf++) {
            const int c = n0w + nf * 8 + 2 * lc;
            *(__half2*)&g_aoh[row0 + c] =
                __floats2half2_rn(O[nf][0] * inv0, O[nf][1] * inv0);
            *(__half2*)&g_aoh[row1 + c] =
                __floats2half2_rn(O[nf][2] * inv1, O[nf][3] * inv1);
        }
    }
}

// ---------------------------------------------------------------------------
// Launch.  Inputs (metadata order):
//  0:q 1:k 2:v 3:p 4:mask(ignored) 5:Wq 6:bq 7:Wk 8:bk 9:Wv 10:bv
//  11:Wp 12:Wo 13:bo 14:bu 15:bv_bias
// ---------------------------------------------------------------------------
extern "C" void kernel_launch(void* const* d_in, const int* in_sizes, int n_in,
                              void* d_out, int out_size) {
    const float* q   = (const float*)d_in[0];
    const float* k   = (const float*)d_in[1];
    const float* v   = (const float*)d_in[2];
    const float* p   = (const float*)d_in[3];
    const float* Wq  = (const float*)d_in[5];
    const float* bq  = (const float*)d_in[6];
    const float* Wk  = (const float*)d_in[7];
    const float* bk  = (const float*)d_in[8];
    const float* Wv  = (const float*)d_in[9];
    const float* bv  = (const float*)d_in[10];
    const float* Wp  = (const float*)d_in[11];
    const float* Wo  = (const float*)d_in[12];
    const float* bo  = (const float*)d_in[13];
    const float* bu  = (const float*)d_in[14];
    const float* bvb = (const float*)d_in[15];
    float* out = (float*)d_out;

    cudaFuncSetAttribute(proj_fp16_kernel, cudaFuncAttributeMaxDynamicSharedMemorySize,
                         (int)PROJ_SMEM_BYTES);
    cudaFuncSetAttribute(out_gemm_fp16_kernel, cudaFuncAttributeMaxDynamicSharedMemorySize,
                         (int)PROJ_SMEM_BYTES);
    cudaFuncSetAttribute(attn_fp16_kernel, cudaFuncAttributeMaxDynamicSharedMemorySize,
                         ATT_BYTES);

    const int M = B * T;  // 4096

    // Single fused fp32 -> fp16 conversion pass (9 segments)
    dim3 cvgrid(192, 9);
    f2h_all_kernel<<<cvgrid, 256>>>(
        (const float4*)q, (const float4*)k, (const float4*)v, (const float4*)p,
        (const float4*)Wq, (const float4*)Wk, (const float4*)Wv, (const float4*)Wp,
        (const float4*)Wo);

    dim3 blk(256);
    dim3 pjgrid(D / 128, (M + 127) / 128, 4);
    proj_fp16_kernel<<<pjgrid, blk, PROJ_SMEM_BYTES>>>(bq, bk, bv);

    dim3 agrid(T / 64, B * H);
    attn_fp16_kernel<<<agrid, 256, ATT_BYTES>>>(bu, bvb);

    dim3 ogrid(D / 128, M / 128, 1);
    out_gemm_fp16_kernel<<<ogrid, blk, PROJ_SMEM_BYTES>>>(bo, out);
}

// round 15
// speedup vs baseline: 1.0260x; 1.0260x over previous
#include <cuda_runtime.h>
#include <cuda_fp16.h>
#include <cstdint>

// Problem constants
constexpr int B  = 2;
constexpr int T  = 2048;
constexpr int D  = 512;
constexpr int H  = 8;
constexpr int DK = 64;         // D / H
constexpr int L  = 2 * T - 1;  // 4095

// ---------------------------------------------------------------------------
// Scratch (no cudaMalloc allowed) — device globals
// ---------------------------------------------------------------------------
__device__ __align__(16) __half g_xq[(size_t)B * T * D];   // fp16 inputs
__device__ __align__(16) __half g_xk[(size_t)B * T * D];
__device__ __align__(16) __half g_xv[(size_t)B * T * D];
__device__ __align__(16) __half g_xp[(size_t)L * D];
__device__ __align__(16) __half g_wq[(size_t)D * D];       // fp16 weights
__device__ __align__(16) __half g_wk[(size_t)D * D];
__device__ __align__(16) __half g_wv[(size_t)D * D];
__device__ __align__(16) __half g_wp[(size_t)D * D];
__device__ __align__(16) __half g_wo[(size_t)D * D];
__device__ __align__(16) __half g_qh[(size_t)B * T * D];   // projected heads
__device__ __align__(16) __half g_kh[(size_t)B * T * D];
__device__ __align__(16) __half g_ph[(size_t)L * D];
__device__ __align__(16) __half g_vht[(size_t)B * H * DK * T];  // V^T per head
__device__ __align__(16) __half g_aoh[(size_t)B * T * D];  // attention out (fp16)

// ---------------------------------------------------------------------------
// Helpers
// ---------------------------------------------------------------------------
__device__ __forceinline__ void mma_f16(float c[4], const uint32_t a[4],
                                        uint32_t b0, uint32_t b1) {
    asm volatile(
        "mma.sync.aligned.m16n8k16.row.col.f32.f16.f16.f32 "
        "{%0,%1,%2,%3}, {%4,%5,%6,%7}, {%8,%9}, {%0,%1,%2,%3};"
        : "+f"(c[0]), "+f"(c[1]), "+f"(c[2]), "+f"(c[3])
        : "r"(a[0]), "r"(a[1]), "r"(a[2]), "r"(a[3]), "r"(b0), "r"(b1));
}

__device__ __forceinline__ void ldsm_x4(uint32_t r[4], uint32_t addr) {
    asm volatile(
        "ldmatrix.sync.aligned.m8n8.x4.shared.b16 {%0,%1,%2,%3}, [%4];"
        : "=r"(r[0]), "=r"(r[1]), "=r"(r[2]), "=r"(r[3]) : "r"(addr));
}

__device__ __forceinline__ uint32_t h2u(__half2 h) {
    return *reinterpret_cast<uint32_t*>(&h);
}

__device__ __forceinline__ float fast_exp2(float x) {
    float r;
    asm("ex2.approx.f32 %0, %1;" : "=f"(r) : "f"(x));
    return r;
}

__device__ __forceinline__ uint32_t s2u(const void* p) {
    return (uint32_t)__cvta_generic_to_shared(p);
}
__device__ __forceinline__ void cp16(uint32_t dst, const void* src) {
    asm volatile("cp.async.ca.shared.global [%0], [%1], 16;" :: "r"(dst), "l"(src));
}
__device__ __forceinline__ void cp_commit() { asm volatile("cp.async.commit_group;"); }
__device__ __forceinline__ void cp_wait0()  { asm volatile("cp.async.wait_group 0;"); }

// ---------------------------------------------------------------------------
// Fused fp32 -> fp16 converter: one launch, 9 segments on blockIdx.y
// ---------------------------------------------------------------------------
__global__ __launch_bounds__(256)
void f2h_all_kernel(const float4* __restrict__ q, const float4* __restrict__ k,
                    const float4* __restrict__ v, const float4* __restrict__ p,
                    const float4* __restrict__ Wq, const float4* __restrict__ Wk,
                    const float4* __restrict__ Wv, const float4* __restrict__ Wp,
                    const float4* __restrict__ Wo) {
    const int seg = blockIdx.y;
    const int nTD4 = B * T * D / 4, nLD4 = L * D / 4, nDD4 = D * D / 4;
    const float4* s;
    uint2* d;
    int n4;
    switch (seg) {
        case 0: s = q;  d = (uint2*)g_xq; n4 = nTD4; break;
        case 1: s = k;  d = (uint2*)g_xk; n4 = nTD4; break;
        case 2: s = v;  d = (uint2*)g_xv; n4 = nTD4; break;
        case 3: s = p;  d = (uint2*)g_xp; n4 = nLD4; break;
        case 4: s = Wq; d = (uint2*)g_wq; n4 = nDD4; break;
        case 5: s = Wk; d = (uint2*)g_wk; n4 = nDD4; break;
        case 6: s = Wv; d = (uint2*)g_wv; n4 = nDD4; break;
        case 7: s = Wp; d = (uint2*)g_wp; n4 = nDD4; break;
        default: s = Wo; d = (uint2*)g_wo; n4 = nDD4; break;
    }
    for (int i = blockIdx.x * blockDim.x + threadIdx.x; i < n4;
         i += gridDim.x * blockDim.x) {
        float4 x = s[i];
        uint2 o;
        o.x = h2u(__floats2half2_rn(x.x, x.y));
        o.y = h2u(__floats2half2_rn(x.z, x.w));
        d[i] = o;
    }
}

// ---------------------------------------------------------------------------
// FP16 GEMM body: Y[M,512] = X[M,512] @ W[512,512]^T + bias
// 128x128 block tile, BK=64, 256 threads, cp.async double buffered, 2 CTA/SM.
// OUT_F32: fp32 output.  VT: write transposed per-head V^T to g_vht instead.
// ---------------------------------------------------------------------------
constexpr int HW = 72;                   // half row stride
constexpr int PBUF = 128 * HW;           // halves per tile buffer
constexpr size_t PROJ_SMEM_BYTES = (size_t)4 * PBUF * sizeof(__half);  // 73728
constexpr int TST = 136;                 // transpose-stage row stride (halves)

template <bool OUT_F32, bool VT>
__device__ __forceinline__ void fp16_gemm_body(const __half* __restrict__ X,
                                               const __half* __restrict__ W,
                                               const float* __restrict__ bias,
                                               void* __restrict__ Yv, int M,
                                               __half* hsm) {
    __half* Xs = hsm;                // 2 buffers
    __half* Ws = hsm + 2 * PBUF;     // 2 buffers

    const int tid = threadIdx.x;
    const int lane = tid & 31, wid = tid >> 5;
    const int wm = wid & 1, wn = wid >> 1;      // 2x4 warps, warp tile 64x32
    const int m0w = wm * 64, n0w = wn * 32;
    const int lr = lane >> 2, lc = lane & 3;
    const int m0 = blockIdx.y * 128, n0 = blockIdx.x * 128;

    const int a_ofs = (m0w + (lane & 15)) * HW + ((lane >> 4) << 3);
    const int b_ofs = (n0w + (lane & 7) + ((lane >> 4) << 3)) * HW
                      + (((lane >> 3) & 1) << 3);

    auto issue = [&](int t, int buf) {
        const int k0 = t * 64;
        __half* Xd = Xs + buf * PBUF;
        __half* Wd = Ws + buf * PBUF;
#pragma unroll
        for (int it = 0; it < 4; it++) {
            int i = tid + it * 256;
            int r = i >> 3, c8 = (i & 7) * 8;
            int gr = m0 + r;
            __half* xd = &Xd[r * HW + c8];
            if (gr < M) cp16(s2u(xd), &X[(size_t)gr * D + k0 + c8]);
            else        *(float4*)xd = make_float4(0.f, 0.f, 0.f, 0.f);
            cp16(s2u(&Wd[r * HW + c8]), &W[(size_t)(n0 + r) * D + k0 + c8]);
        }
    };

    float acc[4][4][4] = {};

    issue(0, 0);
    cp_commit();

    for (int t = 0; t < 8; t++) {
        cp_wait0();
        __syncthreads();
        if (t + 1 < 8) issue(t + 1, (t + 1) & 1);
        cp_commit();

        const __half* Xb = Xs + (t & 1) * PBUF;
        const __half* Wb = Ws + (t & 1) * PBUF;
#pragma unroll
        for (int ks = 0; ks < 4; ks++) {
            const int kk = ks * 16;
            uint32_t a[4][4];
#pragma unroll
            for (int mf = 0; mf < 4; mf++)
                ldsm_x4(a[mf], s2u(Xb + a_ofs + mf * 16 * HW + kk));
#pragma unroll
            for (int nfp = 0; nfp < 2; nfp++) {
                uint32_t bw[4];
                ldsm_x4(bw, s2u(Wb + b_ofs + nfp * 16 * HW + kk));
#pragma unroll
                for (int mf = 0; mf < 4; mf++) {
                    mma_f16(acc[mf][2 * nfp],     a[mf], bw[0], bw[1]);
                    mma_f16(acc[mf][2 * nfp + 1], a[mf], bw[2], bw[3]);
                }
            }
        }
        __syncthreads();
    }

    if (VT) {
        // Stage 128x128 tile transposed in smem: ts[c_local][t_local]
        __half* ts = hsm;
#pragma unroll
        for (int mf = 0; mf < 4; mf++) {
#pragma unroll
            for (int hf = 0; hf < 2; hf++) {
                const int rl = m0w + mf * 16 + hf * 8 + lr;
#pragma unroll
                for (int nf = 0; nf < 4; nf++) {
                    const int cl = n0w + nf * 8 + 2 * lc;
                    ts[cl * TST + rl] =
                        __float2half_rn(acc[mf][nf][hf * 2] + bias[n0 + cl]);
                    ts[(cl + 1) * TST + rl] =
                        __float2half_rn(acc[mf][nf][hf * 2 + 1] + bias[n0 + cl + 1]);
                }
            }
        }
        __syncthreads();
        // Coalesced write-out: g_vht[(b*8+h)*64 + d][t]
        const int b_ = m0 / T, t0_ = m0 % T;
        for (int idx = tid; idx < 128 * 16; idx += 256) {
            const int cl = idx >> 4, t8 = (idx & 15) * 8;
            const int c = n0 + cl;
            const int h_ = c >> 6, d_ = c & 63;
            uint4 vdat = *(const uint4*)&ts[cl * TST + t8];
            *(uint4*)&g_vht[((size_t)(b_ * 8 + h_) * 64 + d_) * T + t0_ + t8] = vdat;
        }
        return;
    }

#pragma unroll
    for (int mf = 0; mf < 4; mf++) {
#pragma unroll
        for (int hf = 0; hf < 2; hf++) {
            const int r = m0 + m0w + mf * 16 + hf * 8 + lr;
            if (r >= M) continue;
#pragma unroll
            for (int nf = 0; nf < 4; nf++) {
                const int c = n0 + n0w + nf * 8 + 2 * lc;
                float b0 = bias ? bias[c] : 0.f;
                float b1 = bias ? bias[c + 1] : 0.f;
                float vx = acc[mf][nf][hf * 2] + b0;
                float vy = acc[mf][nf][hf * 2 + 1] + b1;
                if (OUT_F32) {
                    float* Y = (float*)Yv;
                    *(float2*)&Y[(size_t)r * D + c] = make_float2(vx, vy);
                } else {
                    __half* Y = (__half*)Yv;
                    *(__half2*)&Y[(size_t)r * D + c] = __floats2half2_rn(vx, vy);
                }
            }
        }
    }
}

__global__ __launch_bounds__(256, 2)
void proj_fp16_kernel(const float* __restrict__ bq, const float* __restrict__ bk,
                      const float* __restrict__ bv) {
    extern __shared__ __align__(16) __half hsm[];
    const int z = blockIdx.z;
    if (z == 2) {
        // V projection: write transposed per-head layout directly
        fp16_gemm_body<false, true>(g_xv, g_wv, bv, nullptr, B * T, hsm);
        return;
    }
    const __half* X = (z == 0) ? g_xq : (z == 1) ? g_xk : g_xp;
    const __half* W = (z == 0) ? g_wq : (z == 1) ? g_wk : g_wp;
    const float* bias = (z == 0) ? bq : (z == 1) ? bk : nullptr;
    __half* Y = (z == 0) ? g_qh : (z == 1) ? g_kh : g_ph;
    const int M = (z == 3) ? L : B * T;
    fp16_gemm_body<false, false>(X, W, bias, Y, M, hsm);
}

// ---------------------------------------------------------------------------
// Output GEMM, retiled 128x64 (grid 256) for full-chip coverage.
// 8 warps in 4x2 grid, warp tile 32x32; BK=64, cp.async double buffered.
// ---------------------------------------------------------------------------
constexpr int OBUF_X = 128 * HW;         // X tile halves
constexpr int OBUF_W = 64 * HW;          // W tile halves
constexpr size_t OUT_SMEM_BYTES =
    (size_t)(2 * OBUF_X + 2 * OBUF_W) * sizeof(__half);  // 55296

__global__ __launch_bounds__(256, 2)
void out_gemm_fp16_kernel(const float* __restrict__ bo, float* __restrict__ Y) {
    extern __shared__ __align__(16) __half hsm[];
    __half* Xs = hsm;                    // 2 buffers
    __half* Ws = hsm + 2 * OBUF_X;       // 2 buffers

    const __half* X = g_aoh;
    const __half* W = g_wo;

    const int tid = threadIdx.x;
    const int lane = tid & 31, wid = tid >> 5;
    const int wm = wid & 3, wn = wid >> 2;      // 4x2 warps, warp tile 32x32
    const int m0w = wm * 32, n0w = wn * 32;
    const int lr = lane >> 2, lc = lane & 3;
    const int m0 = blockIdx.y * 128, n0 = blockIdx.x * 64;

    const int a_ofs = (m0w + (lane & 15)) * HW + ((lane >> 4) << 3);
    const int b_ofs = (n0w + (lane & 7) + ((lane >> 4) << 3)) * HW
                      + (((lane >> 3) & 1) << 3);

    auto issue = [&](int t, int buf) {
        const int k0 = t * 64;
        __half* Xd = Xs + buf * OBUF_X;
        __half* Wd = Ws + buf * OBUF_W;
#pragma unroll
        for (int it = 0; it < 4; it++) {
            int i = tid + it * 256;
            int r = i >> 3, c8 = (i & 7) * 8;
            cp16(s2u(&Xd[r * HW + c8]), &X[(size_t)(m0 + r) * D + k0 + c8]);
        }
#pragma unroll
        for (int it = 0; it < 2; it++) {
            int i = tid + it * 256;
            int r = i >> 3, c8 = (i & 7) * 8;
            cp16(s2u(&Wd[r * HW + c8]), &W[(size_t)(n0 + r) * D + k0 + c8]);
        }
    };

    float acc[2][4][4] = {};

    issue(0, 0);
    cp_commit();

    for (int t = 0; t < 8; t++) {
        cp_wait0();
        __syncthreads();
        if (t + 1 < 8) issue(t + 1, (t + 1) & 1);
        cp_commit();

        const __half* Xb = Xs + (t & 1) * OBUF_X;
        const __half* Wb = Ws + (t & 1) * OBUF_W;
#pragma unroll
        for (int ks = 0; ks < 4; ks++) {
            const int kk = ks * 16;
            uint32_t a[2][4];
#pragma unroll
            for (int mf = 0; mf < 2; mf++)
                ldsm_x4(a[mf], s2u(Xb + a_ofs + mf * 16 * HW + kk));
#pragma unroll
            for (int nfp = 0; nfp < 2; nfp++) {
                uint32_t bw[4];
                ldsm_x4(bw, s2u(Wb + b_ofs + nfp * 16 * HW + kk));
#pragma unroll
                for (int mf = 0; mf < 2; mf++) {
                    mma_f16(acc[mf][2 * nfp],     a[mf], bw[0], bw[1]);
                    mma_f16(acc[mf][2 * nfp + 1], a[mf], bw[2], bw[3]);
                }
            }
        }
        __syncthreads();
    }

#pragma unroll
    for (int mf = 0; mf < 2; mf++) {
#pragma unroll
        for (int hf = 0; hf < 2; hf++) {
            const int r = m0 + m0w + mf * 16 + hf * 8 + lr;
#pragma unroll
            for (int nf = 0; nf < 4; nf++) {
                const int c = n0 + n0w + nf * 8 + 2 * lc;
                *(float2*)&Y[(size_t)r * D + c] =
                    make_float2(acc[mf][nf][hf * 2] + bo[c],
                                acc[mf][nf][hf * 2 + 1] + bo[c + 1]);
            }
        }
    }
}

// ---------------------------------------------------------------------------
// Rel-pos flash attention (R13 structure, unchanged): fragment softmax,
// ldmatrix loads, scale folded into Q fragments, 3 barriers per k-tile.
// ---------------------------------------------------------------------------
constexpr int HP  = 72;
constexpr int RST = 132;
constexpr int TILE_HB = 64 * HP * 2;    // 9216 bytes

constexpr int OFF_K  = 0;                        // 2 buffers
constexpr int OFF_VT = OFF_K  + 2 * TILE_HB;     // 2 buffers
constexpr int OFF_P  = OFF_VT + 2 * TILE_HB;     // 2 buffers
constexpr int OFF_PH = OFF_P  + 2 * TILE_HB;     // 64 x 72 half (Q stage / probs)
constexpr int OFF_BD = OFF_PH + TILE_HB;         // 64 x 132 half ring
constexpr int OFF_LS = OFF_BD + 64 * RST * 2;    // 128 floats
constexpr int ATT_BYTES = OFF_LS + 128 * 4;      // 82432 bytes

__global__ __launch_bounds__(256, 2)
void attn_fp16_kernel(const float* __restrict__ bu, const float* __restrict__ bvb) {
    extern __shared__ __align__(16) char smx[];
    __half* Ks  = (__half*)(smx + OFF_K);
    __half* Vts = (__half*)(smx + OFF_VT);
    __half* Ps  = (__half*)(smx + OFF_P);
    __half* Ph  = (__half*)(smx + OFF_PH);
    __half* BDh = (__half*)(smx + OFF_BD);
    float*  LS  = (float*) (smx + OFF_LS);

    const int tid = threadIdx.x;
    const int lane = tid & 31, wid = tid >> 5;
    const int wm = wid & 3, wn = wid >> 2;          // 4x2 warp grid
    const int m0w = wm * 16, n0w = wn * 32;         // warp tile 16x32
    const int lr = lane >> 2, lc = lane & 3;

    const int a_ofs = (m0w + (lane & 15)) * HP + ((lane >> 4) << 3);
    const int b_ofs = (n0w + (lane & 7) + ((lane >> 4) << 3)) * HP
                      + (((lane >> 3) & 1) << 3);

    const int q0 = blockIdx.x * 64;
    const int bh = blockIdx.y;
    const int b = bh >> 3, h = bh & 7;
    const int base_p = T - 1 - q0 - 63;   // >= 0

    const __half* qb = g_qh + (size_t)b * T * D + h * DK;
    const __half* kb = g_kh + (size_t)b * T * D + h * DK;
    const __half* vtb = g_vht + (size_t)bh * DK * T;
    const __half* pb = g_ph + h * DK;

    auto issue_kv = [&](int kt, int buf) {
        const __half* kbase = kb + (size_t)(kt * 64) * D;
        const __half* vbase = vtb + kt * 64;
        __half* Kd = Ks + buf * (64 * HP);
        __half* Vd = Vts + buf * (64 * HP);
#pragma unroll
        for (int it = 0; it < 2; it++) {
            int i = tid + it * 256;
            int r = i >> 3, c8 = (i & 7) * 8;
            cp16(s2u(&Kd[r * HP + c8]), kbase + (size_t)r * D + c8);
            cp16(s2u(&Vd[r * HP + c8]), vbase + (size_t)r * T + c8);
        }
    };
    auto issue_p = [&](int ch, int buf) {
        __half* Pd = Ps + buf * (64 * HP);
#pragma unroll
        for (int it = 0; it < 2; it++) {
            int i = tid + it * 256;
            int r = i >> 3, c8 = (i & 7) * 8;
            int g = base_p + ch * 64 + r;
            __half* dst = &Pd[r * HP + c8];
            if (g < L) cp16(s2u(dst), pb + (size_t)g * D + c8);
            else       *(float4*)dst = make_float4(0.f, 0.f, 0.f, 0.f);
        }
    };

    // ---- stage Q into Ph, build register A-fragments with bias+scale ----
#pragma unroll
    for (int it = 0; it < 2; it++) {
        int i = tid + it * 256;
        int r = i >> 3, c8 = (i & 7) * 8;
        cp16(s2u(&Ph[r * HP + c8]), qb + (size_t)(q0 + r) * D + c8);
    }
    cp_commit();
    cp_wait0();
    __syncthreads();

    constexpr float SCQ = 0.125f * 1.4426950408889634f;  // 1/sqrt(64) * log2(e)
    const int rA = m0w + lr, rB = rA + 8;
    uint32_t qf1[4][4], qf2[4][4];
#pragma unroll
    for (int ks = 0; ks < 4; ks++) {
        const int cc = ks * 16 + 2 * lc;
        float2 buL = *(const float2*)&bu[h * DK + cc];
        float2 buH = *(const float2*)&bu[h * DK + cc + 8];
        float2 bvL = *(const float2*)&bvb[h * DK + cc];
        float2 bvH = *(const float2*)&bvb[h * DK + cc + 8];
        float2 qaL = __half22float2(*(const __half2*)&Ph[rA * HP + cc]);
        float2 qbL = __half22float2(*(const __half2*)&Ph[rB * HP + cc]);
        float2 qaH = __half22float2(*(const __half2*)&Ph[rA * HP + cc + 8]);
        float2 qbH = __half22float2(*(const __half2*)&Ph[rB * HP + cc + 8]);
        qf1[ks][0] = h2u(__floats2half2_rn((qaL.x + buL.x) * SCQ, (qaL.y + buL.y) * SCQ));
        qf1[ks][1] = h2u(__floats2half2_rn((qbL.x + buL.x) * SCQ, (qbL.y + buL.y) * SCQ));
        qf1[ks][2] = h2u(__floats2half2_rn((qaH.x + buH.x) * SCQ, (qaH.y + buH.y) * SCQ));
        qf1[ks][3] = h2u(__floats2half2_rn((qbH.x + buH.x) * SCQ, (qbH.y + buH.y) * SCQ));
        qf2[ks][0] = h2u(__floats2half2_rn((qaL.x + bvL.x) * SCQ, (qaL.y + bvL.y) * SCQ));
        qf2[ks][1] = h2u(__floats2half2_rn((qbL.x + bvL.x) * SCQ, (qbL.y + bvL.y) * SCQ));
        qf2[ks][2] = h2u(__floats2half2_rn((qaH.x + bvH.x) * SCQ, (qaH.y + bvH.y) * SCQ));
        qf2[ks][3] = h2u(__floats2half2_rn((qbH.x + bvH.x) * SCQ, (qbH.y + bvH.y) * SCQ));
    }
    __syncthreads();   // Ph now free for probs

    issue_kv(0, 0);
    issue_p(0, 0);
    issue_p(1, 1);
    cp_commit();
    cp_wait0();
    __syncthreads();

    // ---- prologue: BD chunk 0 -> ring slot 0 ----
    {
        const __half* Pb = Ps;  // buf 0
        float accB[4][4] = {};
#pragma unroll
        for (int ks = 0; ks < 4; ks++) {
            const int kk = ks * 16;
#pragma unroll
            for (int nfp = 0; nfp < 2; nfp++) {
                uint32_t bp_[4];
                ldsm_x4(bp_, s2u(Pb + b_ofs + nfp * 16 * HP + kk));
                mma_f16(accB[2 * nfp],     qf2[ks], bp_[0], bp_[1]);
                mma_f16(accB[2 * nfp + 1], qf2[ks], bp_[2], bp_[3]);
            }
        }
#pragma unroll
        for (int nf = 0; nf < 4; nf++) {
            const int cr = n0w + nf * 8 + 2 * lc;
            uint32_t lo = h2u(__floats2half2_rn(accB[nf][0], accB[nf][1]));
            uint32_t hi = h2u(__floats2half2_rn(accB[nf][2], accB[nf][3]));
            *(uint32_t*)&BDh[rA * RST + cr] = lo;
            *(uint32_t*)&BDh[rB * RST + cr] = hi;
            if (cr < 4) {
                *(uint32_t*)&BDh[rA * RST + cr + 128] = lo;
                *(uint32_t*)&BDh[rB * RST + cr + 128] = hi;
            }
        }
    }
    __syncthreads();

    float O[4][4] = {};
    float lsumA = 0.f, lsumB = 0.f;

    for (int kt = 0; kt < 32; kt++) {
        if (kt + 1 < 32) issue_kv(kt + 1, (kt + 1) & 1);
        if (kt + 2 <= 32) issue_p(kt + 2, kt & 1);
        cp_commit();

        // --- (a) AC (regs) + BD chunk kt+1 (regs); write ring slot kt+1 ---
        const __half* Kb = Ks + (kt & 1) * (64 * HP);
        const __half* Pb = Ps + ((kt + 1) & 1) * (64 * HP);
        float accA[4][4] = {};
        {
            float accB[4][4] = {};
#pragma unroll
            for (int ks = 0; ks < 4; ks++) {
                const int kk = ks * 16;
#pragma unroll
                for (int nfp = 0; nfp < 2; nfp++) {
                    uint32_t bk_[4], bp_[4];
                    ldsm_x4(bk_, s2u(Kb + b_ofs + nfp * 16 * HP + kk));
                    mma_f16(accA[2 * nfp],     qf1[ks], bk_[0], bk_[1]);
                    mma_f16(accA[2 * nfp + 1], qf1[ks], bk_[2], bk_[3]);
                    ldsm_x4(bp_, s2u(Pb + b_ofs + nfp * 16 * HP + kk));
                    mma_f16(accB[2 * nfp],     qf2[ks], bp_[0], bp_[1]);
                    mma_f16(accB[2 * nfp + 1], qf2[ks], bp_[2], bp_[3]);
                }
            }
            const int slotc = ((kt + 1) & 1) * 64;
#pragma unroll
            for (int nf = 0; nf < 4; nf++) {
                const int cr = slotc + n0w + nf * 8 + 2 * lc;
                uint32_t lo = h2u(__floats2half2_rn(accB[nf][0], accB[nf][1]));
                uint32_t hi = h2u(__floats2half2_rn(accB[nf][2], accB[nf][3]));
                *(uint32_t*)&BDh[rA * RST + cr] = lo;
                *(uint32_t*)&BDh[rB * RST + cr] = hi;
                if (cr < 4) {
                    *(uint32_t*)&BDh[rA * RST + cr + 128] = lo;
                    *(uint32_t*)&BDh[rB * RST + cr + 128] = hi;
                }
            }
        }
        __syncthreads();   // ring complete: tile-kt window (both slots) valid

        // --- (b) fragment softmax on AC regs + ring reads -> probs in Ph ---
        {
            const int base_w = 63 + 64 * kt;
#pragma unroll
            for (int nf = 0; nf < 4; nf++) {
                const int c = n0w + nf * 8 + 2 * lc;
                const int wbA = (base_w - rA + c) & 127;
                const int wbB = (base_w - rB + c) & 127;
                float p0 = fast_exp2(accA[nf][0] + __half2float(BDh[rA * RST + wbA]));
                float p1 = fast_exp2(accA[nf][1] + __half2float(BDh[rA * RST + wbA + 1]));
                float p2 = fast_exp2(accA[nf][2] + __half2float(BDh[rB * RST + wbB]));
                float p3 = fast_exp2(accA[nf][3] + __half2float(BDh[rB * RST + wbB + 1]));
                lsumA += p0 + p1;
                lsumB += p2 + p3;
                *(uint32_t*)&Ph[rA * HP + c] = h2u(__floats2half2_rn(p0, p1));
                *(uint32_t*)&Ph[rB * HP + c] = h2u(__floats2half2_rn(p2, p3));
            }
        }
        __syncthreads();   // probs visible; ring slot-kt reads done

        // --- (c) P@V ---
        {
            const __half* Vb = Vts + (kt & 1) * (64 * HP);
#pragma unroll
            for (int ks = 0; ks < 4; ks++) {
                const int kk = ks * 16;
                uint32_t a[4];
                ldsm_x4(a, s2u(Ph + a_ofs + kk));
#pragma unroll
                for (int nfp = 0; nfp < 2; nfp++) {
                    uint32_t bv_[4];
                    ldsm_x4(bv_, s2u(Vb + b_ofs + nfp * 16 * HP + kk));
                    mma_f16(O[2 * nfp],     a, bv_[0], bv_[1]);
                    mma_f16(O[2 * nfp + 1], a, bv_[2], bv_[3]);
                }
            }
        }
        cp_wait0();
        __syncthreads();   // buffers ready, Ph free
    }

    // ---- final row-sum: quad shfl + 2-warp smem combine ----
    lsumA += __shfl_xor_sync(0xffffffffu, lsumA, 1);
    lsumA += __shfl_xor_sync(0xffffffffu, lsumA, 2);
    lsumB += __shfl_xor_sync(0xffffffffu, lsumB, 1);
    lsumB += __shfl_xor_sync(0xffffffffu, lsumB, 2);
    if (lc == 0) {
        LS[wn * 64 + rA] = lsumA;
        LS[wn * 64 + rB] = lsumB;
    }
    __syncthreads();

    {
        const float inv0 = 1.f / (LS[rA] + LS[64 + rA]);
        const float inv1 = 1.f / (LS[rB] + LS[64 + rB]);
        const size_t row0 = (size_t)(b * T + q0 + rA) * D + h * DK;
        const size_t row1 = row0 + (size_t)8 * D;
#pragma unroll
        for (int nf = 0; nf < 4; nf++) {
            const int c = n0w + nf * 8 + 2 * lc;
            *(__half2*)&g_aoh[row0 + c] =
                __floats2half2_rn(O[nf][0] * inv0, O[nf][1] * inv0);
            *(__half2*)&g_aoh[row1 + c] =
                __floats2half2_rn(O[nf][2] * inv1, O[nf][3] * inv1);
        }
    }
}

// ---------------------------------------------------------------------------
// Launch.  Inputs (metadata order):
//  0:q 1:k 2:v 3:p 4:mask(ignored) 5:Wq 6:bq 7:Wk 8:bk 9:Wv 10:bv
//  11:Wp 12:Wo 13:bo 14:bu 15:bv_bias
// ---------------------------------------------------------------------------
extern "C" void kernel_launch(void* const* d_in, const int* in_sizes, int n_in,
                              void* d_out, int out_size) {
    const float* q   = (const float*)d_in[0];
    const float* k   = (const float*)d_in[1];
    const float* v   = (const float*)d_in[2];
    const float* p   = (const float*)d_in[3];
    const float* Wq  = (const float*)d_in[5];
    const float* bq  = (const float*)d_in[6];
    const float* Wk  = (const float*)d_in[7];
    const float* bk  = (const float*)d_in[8];
    const float* Wv  = (const float*)d_in[9];
    const float* bv  = (const float*)d_in[10];
    const float* Wp  = (const float*)d_in[11];
    const float* Wo  = (const float*)d_in[12];
    const float* bo  = (const float*)d_in[13];
    const float* bu  = (const float*)d_in[14];
    const float* bvb = (const float*)d_in[15];
    float* out = (float*)d_out;

    cudaFuncSetAttribute(proj_fp16_kernel, cudaFuncAttributeMaxDynamicSharedMemorySize,
                         (int)PROJ_SMEM_BYTES);
    cudaFuncSetAttribute(out_gemm_fp16_kernel, cudaFuncAttributeMaxDynamicSharedMemorySize,
                         (int)OUT_SMEM_BYTES);
    cudaFuncSetAttribute(attn_fp16_kernel, cudaFuncAttributeMaxDynamicSharedMemorySize,
                         ATT_BYTES);

    const int M = B * T;  // 4096

    // Single fused fp32 -> fp16 conversion pass (9 segments)
    dim3 cvgrid(192, 9);
    f2h_all_kernel<<<cvgrid, 256>>>(
        (const float4*)q, (const float4*)k, (const float4*)v, (const float4*)p,
        (const float4*)Wq, (const float4*)Wk, (const float4*)Wv, (const float4*)Wp,
        (const float4*)Wo);

    dim3 blk(256);
    dim3 pjgrid(D / 128, (M + 127) / 128, 4);
    proj_fp16_kernel<<<pjgrid, blk, PROJ_SMEM_BYTES>>>(bq, bk, bv);

    dim3 agrid(T / 64, B * H);
    attn_fp16_kernel<<<agrid, 256, ATT_BYTES>>>(bu, bvb);

    dim3 ogrid(D / 64, M / 128, 1);   // 8 x 32 = 256 blocks
    out_gemm_fp16_kernel<<<ogrid, blk, OUT_SMEM_BYTES>>>(bo, out);
}

// round 16
// speedup vs baseline: 1.0386x; 1.0123x over previous
#include <cuda_runtime.h>
#include <cuda_fp16.h>
#include <cstdint>

// Problem constants
constexpr int B  = 2;
constexpr int T  = 2048;
constexpr int D  = 512;
constexpr int H  = 8;
constexpr int DK = 64;         // D / H
constexpr int L  = 2 * T - 1;  // 4095

// ---------------------------------------------------------------------------
// Scratch (no cudaMalloc allowed) — device globals
// ---------------------------------------------------------------------------
__device__ __align__(16) __half g_xq[(size_t)B * T * D];   // fp16 inputs
__device__ __align__(16) __half g_xk[(size_t)B * T * D];
__device__ __align__(16) __half g_xv[(size_t)B * T * D];
__device__ __align__(16) __half g_xp[(size_t)L * D];
__device__ __align__(16) __half g_wq[(size_t)D * D];       // fp16 weights
__device__ __align__(16) __half g_wk[(size_t)D * D];
__device__ __align__(16) __half g_wv[(size_t)D * D];
__device__ __align__(16) __half g_wp[(size_t)D * D];
__device__ __align__(16) __half g_wo[(size_t)D * D];
__device__ __align__(16) __half g_qh[(size_t)B * T * D];   // projected heads
__device__ __align__(16) __half g_kh[(size_t)B * T * D];
__device__ __align__(16) __half g_ph[(size_t)L * D];
__device__ __align__(16) __half g_vht[(size_t)B * H * DK * T];  // V^T per head
__device__ __align__(16) __half g_aoh[(size_t)B * T * D];  // attention out (fp16)

// ---------------------------------------------------------------------------
// Helpers
// ---------------------------------------------------------------------------
__device__ __forceinline__ void mma_f16(float c[4], const uint32_t a[4],
                                        uint32_t b0, uint32_t b1) {
    asm volatile(
        "mma.sync.aligned.m16n8k16.row.col.f32.f16.f16.f32 "
        "{%0,%1,%2,%3}, {%4,%5,%6,%7}, {%8,%9}, {%0,%1,%2,%3};"
        : "+f"(c[0]), "+f"(c[1]), "+f"(c[2]), "+f"(c[3])
        : "r"(a[0]), "r"(a[1]), "r"(a[2]), "r"(a[3]), "r"(b0), "r"(b1));
}

__device__ __forceinline__ void ldsm_x4(uint32_t r[4], uint32_t addr) {
    asm volatile(
        "ldmatrix.sync.aligned.m8n8.x4.shared.b16 {%0,%1,%2,%3}, [%4];"
        : "=r"(r[0]), "=r"(r[1]), "=r"(r[2]), "=r"(r[3]) : "r"(addr));
}

__device__ __forceinline__ uint32_t h2u(__half2 h) {
    return *reinterpret_cast<uint32_t*>(&h);
}

__device__ __forceinline__ float fast_exp2(float x) {
    float r;
    asm("ex2.approx.f32 %0, %1;" : "=f"(r) : "f"(x));
    return r;
}

__device__ __forceinline__ uint32_t s2u(const void* p) {
    return (uint32_t)__cvta_generic_to_shared(p);
}
// L1-bypass async copy (.cg): data is consumed only via SMEM, so skip L1 alloc.
__device__ __forceinline__ void cp16(uint32_t dst, const void* src) {
    asm volatile("cp.async.cg.shared.global [%0], [%1], 16;" :: "r"(dst), "l"(src));
}
__device__ __forceinline__ void cp_commit() { asm volatile("cp.async.commit_group;"); }
__device__ __forceinline__ void cp_wait0()  { asm volatile("cp.async.wait_group 0;"); }

// ---------------------------------------------------------------------------
// Fused fp32 -> fp16 converter: one launch, 9 segments on blockIdx.y
// ---------------------------------------------------------------------------
__global__ __launch_bounds__(256)
void f2h_all_kernel(const float4* __restrict__ q, const float4* __restrict__ k,
                    const float4* __restrict__ v, const float4* __restrict__ p,
                    const float4* __restrict__ Wq, const float4* __restrict__ Wk,
                    const float4* __restrict__ Wv, const float4* __restrict__ Wp,
                    const float4* __restrict__ Wo) {
    const int seg = blockIdx.y;
    const int nTD4 = B * T * D / 4, nLD4 = L * D / 4, nDD4 = D * D / 4;
    const float4* s;
    uint2* d;
    int n4;
    switch (seg) {
        case 0: s = q;  d = (uint2*)g_xq; n4 = nTD4; break;
        case 1: s = k;  d = (uint2*)g_xk; n4 = nTD4; break;
        case 2: s = v;  d = (uint2*)g_xv; n4 = nTD4; break;
        case 3: s = p;  d = (uint2*)g_xp; n4 = nLD4; break;
        case 4: s = Wq; d = (uint2*)g_wq; n4 = nDD4; break;
        case 5: s = Wk; d = (uint2*)g_wk; n4 = nDD4; break;
        case 6: s = Wv; d = (uint2*)g_wv; n4 = nDD4; break;
        case 7: s = Wp; d = (uint2*)g_wp; n4 = nDD4; break;
        default: s = Wo; d = (uint2*)g_wo; n4 = nDD4; break;
    }
    for (int i = blockIdx.x * blockDim.x + threadIdx.x; i < n4;
         i += gridDim.x * blockDim.x) {
        float4 x = s[i];
        uint2 o;
        o.x = h2u(__floats2half2_rn(x.x, x.y));
        o.y = h2u(__floats2half2_rn(x.z, x.w));
        d[i] = o;
    }
}

// ---------------------------------------------------------------------------
// FP16 GEMM body: Y[M,512] = X[M,512] @ W[512,512]^T + bias
// 128x128 block tile, BK=64, 256 threads, cp.async double buffered, 2 CTA/SM.
// OUT_F32: fp32 output.  VT: write transposed per-head V^T to g_vht instead.
// ---------------------------------------------------------------------------
constexpr int HW = 72;                   // half row stride
constexpr int PBUF = 128 * HW;           // halves per tile buffer
constexpr size_t PROJ_SMEM_BYTES = (size_t)4 * PBUF * sizeof(__half);  // 73728
constexpr int TST = 136;                 // transpose-stage row stride (halves)

template <bool OUT_F32, bool VT>
__device__ __forceinline__ void fp16_gemm_body(const __half* __restrict__ X,
                                               const __half* __restrict__ W,
                                               const float* __restrict__ bias,
                                               void* __restrict__ Yv, int M,
                                               __half* hsm) {
    __half* Xs = hsm;                // 2 buffers
    __half* Ws = hsm + 2 * PBUF;     // 2 buffers

    const int tid = threadIdx.x;
    const int lane = tid & 31, wid = tid >> 5;
    const int wm = wid & 1, wn = wid >> 1;      // 2x4 warps, warp tile 64x32
    const int m0w = wm * 64, n0w = wn * 32;
    const int lr = lane >> 2, lc = lane & 3;
    const int m0 = blockIdx.y * 128, n0 = blockIdx.x * 128;

    const int a_ofs = (m0w + (lane & 15)) * HW + ((lane >> 4) << 3);
    const int b_ofs = (n0w + (lane & 7) + ((lane >> 4) << 3)) * HW
                      + (((lane >> 3) & 1) << 3);

    auto issue = [&](int t, int buf) {
        const int k0 = t * 64;
        __half* Xd = Xs + buf * PBUF;
        __half* Wd = Ws + buf * PBUF;
#pragma unroll
        for (int it = 0; it < 4; it++) {
            int i = tid + it * 256;
            int r = i >> 3, c8 = (i & 7) * 8;
            int gr = m0 + r;
            __half* xd = &Xd[r * HW + c8];
            if (gr < M) cp16(s2u(xd), &X[(size_t)gr * D + k0 + c8]);
            else        *(float4*)xd = make_float4(0.f, 0.f, 0.f, 0.f);
            cp16(s2u(&Wd[r * HW + c8]), &W[(size_t)(n0 + r) * D + k0 + c8]);
        }
    };

    float acc[4][4][4] = {};

    issue(0, 0);
    cp_commit();

    for (int t = 0; t < 8; t++) {
        cp_wait0();
        __syncthreads();
        if (t + 1 < 8) issue(t + 1, (t + 1) & 1);
        cp_commit();

        const __half* Xb = Xs + (t & 1) * PBUF;
        const __half* Wb = Ws + (t & 1) * PBUF;
#pragma unroll
        for (int ks = 0; ks < 4; ks++) {
            const int kk = ks * 16;
            uint32_t a[4][4];
#pragma unroll
            for (int mf = 0; mf < 4; mf++)
                ldsm_x4(a[mf], s2u(Xb + a_ofs + mf * 16 * HW + kk));
#pragma unroll
            for (int nfp = 0; nfp < 2; nfp++) {
                uint32_t bw[4];
                ldsm_x4(bw, s2u(Wb + b_ofs + nfp * 16 * HW + kk));
#pragma unroll
                for (int mf = 0; mf < 4; mf++) {
                    mma_f16(acc[mf][2 * nfp],     a[mf], bw[0], bw[1]);
                    mma_f16(acc[mf][2 * nfp + 1], a[mf], bw[2], bw[3]);
                }
            }
        }
        __syncthreads();
    }

    if (VT) {
        // Stage 128x128 tile transposed in smem: ts[c_local][t_local]
        __half* ts = hsm;
#pragma unroll
        for (int mf = 0; mf < 4; mf++) {
#pragma unroll
            for (int hf = 0; hf < 2; hf++) {
                const int rl = m0w + mf * 16 + hf * 8 + lr;
#pragma unroll
                for (int nf = 0; nf < 4; nf++) {
                    const int cl = n0w + nf * 8 + 2 * lc;
                    ts[cl * TST + rl] =
                        __float2half_rn(acc[mf][nf][hf * 2] + bias[n0 + cl]);
                    ts[(cl + 1) * TST + rl] =
                        __float2half_rn(acc[mf][nf][hf * 2 + 1] + bias[n0 + cl + 1]);
                }
            }
        }
        __syncthreads();
        // Coalesced write-out: g_vht[(b*8+h)*64 + d][t]
        const int b_ = m0 / T, t0_ = m0 % T;
        for (int idx = tid; idx < 128 * 16; idx += 256) {
            const int cl = idx >> 4, t8 = (idx & 15) * 8;
            const int c = n0 + cl;
            const int h_ = c >> 6, d_ = c & 63;
            uint4 vdat = *(const uint4*)&ts[cl * TST + t8];
            *(uint4*)&g_vht[((size_t)(b_ * 8 + h_) * 64 + d_) * T + t0_ + t8] = vdat;
        }
        return;
    }

#pragma unroll
    for (int mf = 0; mf < 4; mf++) {
#pragma unroll
        for (int hf = 0; hf < 2; hf++) {
            const int r = m0 + m0w + mf * 16 + hf * 8 + lr;
            if (r >= M) continue;
#pragma unroll
            for (int nf = 0; nf < 4; nf++) {
                const int c = n0 + n0w + nf * 8 + 2 * lc;
                float b0 = bias ? bias[c] : 0.f;
                float b1 = bias ? bias[c + 1] : 0.f;
                float vx = acc[mf][nf][hf * 2] + b0;
                float vy = acc[mf][nf][hf * 2 + 1] + b1;
                if (OUT_F32) {
                    float* Y = (float*)Yv;
                    *(float2*)&Y[(size_t)r * D + c] = make_float2(vx, vy);
                } else {
                    __half* Y = (__half*)Yv;
                    *(__half2*)&Y[(size_t)r * D + c] = __floats2half2_rn(vx, vy);
                }
            }
        }
    }
}

__global__ __launch_bounds__(256, 2)
void proj_fp16_kernel(const float* __restrict__ bq, const float* __restrict__ bk,
                      const float* __restrict__ bv) {
    extern __shared__ __align__(16) __half hsm[];
    const int z = blockIdx.z;
    if (z == 2) {
        // V projection: write transposed per-head layout directly
        fp16_gemm_body<false, true>(g_xv, g_wv, bv, nullptr, B * T, hsm);
        return;
    }
    const __half* X = (z == 0) ? g_xq : (z == 1) ? g_xk : g_xp;
    const __half* W = (z == 0) ? g_wq : (z == 1) ? g_wk : g_wp;
    const float* bias = (z == 0) ? bq : (z == 1) ? bk : nullptr;
    __half* Y = (z == 0) ? g_qh : (z == 1) ? g_kh : g_ph;
    const int M = (z == 3) ? L : B * T;
    fp16_gemm_body<false, false>(X, W, bias, Y, M, hsm);
}

// ---------------------------------------------------------------------------
// Output GEMM, retiled 128x64 (grid 256) for full-chip coverage.
// 8 warps in 4x2 grid, warp tile 32x32; BK=64, cp.async double buffered.
// ---------------------------------------------------------------------------
constexpr int OBUF_X = 128 * HW;         // X tile halves
constexpr int OBUF_W = 64 * HW;          // W tile halves
constexpr size_t OUT_SMEM_BYTES =
    (size_t)(2 * OBUF_X + 2 * OBUF_W) * sizeof(__half);  // 55296

__global__ __launch_bounds__(256, 2)
void out_gemm_fp16_kernel(const float* __restrict__ bo, float* __restrict__ Y) {
    extern __shared__ __align__(16) __half hsm[];
    __half* Xs = hsm;                    // 2 buffers
    __half* Ws = hsm + 2 * OBUF_X;       // 2 buffers

    const __half* X = g_aoh;
    const __half* W = g_wo;

    const int tid = threadIdx.x;
    const int lane = tid & 31, wid = tid >> 5;
    const int wm = wid & 3, wn = wid >> 2;      // 4x2 warps, warp tile 32x32
    const int m0w = wm * 32, n0w = wn * 32;
    const int lr = lane >> 2, lc = lane & 3;
    const int m0 = blockIdx.y * 128, n0 = blockIdx.x * 64;

    const int a_ofs = (m0w + (lane & 15)) * HW + ((lane >> 4) << 3);
    const int b_ofs = (n0w + (lane & 7) + ((lane >> 4) << 3)) * HW
                      + (((lane >> 3) & 1) << 3);

    auto issue = [&](int t, int buf) {
        const int k0 = t * 64;
        __half* Xd = Xs + buf * OBUF_X;
        __half* Wd = Ws + buf * OBUF_W;
#pragma unroll
        for (int it = 0; it < 4; it++) {
            int i = tid + it * 256;
            int r = i >> 3, c8 = (i & 7) * 8;
            cp16(s2u(&Xd[r * HW + c8]), &X[(size_t)(m0 + r) * D + k0 + c8]);
        }
#pragma unroll
        for (int it = 0; it < 2; it++) {
            int i = tid + it * 256;
            int r = i >> 3, c8 = (i & 7) * 8;
            cp16(s2u(&Wd[r * HW + c8]), &W[(size_t)(n0 + r) * D + k0 + c8]);
        }
    };

    float acc[2][4][4] = {};

    issue(0, 0);
    cp_commit();

    for (int t = 0; t < 8; t++) {
        cp_wait0();
        __syncthreads();
        if (t + 1 < 8) issue(t + 1, (t + 1) & 1);
        cp_commit();

        const __half* Xb = Xs + (t & 1) * OBUF_X;
        const __half* Wb = Ws + (t & 1) * OBUF_W;
#pragma unroll
        for (int ks = 0; ks < 4; ks++) {
            const int kk = ks * 16;
            uint32_t a[2][4];
#pragma unroll
            for (int mf = 0; mf < 2; mf++)
                ldsm_x4(a[mf], s2u(Xb + a_ofs + mf * 16 * HW + kk));
#pragma unroll
            for (int nfp = 0; nfp < 2; nfp++) {
                uint32_t bw[4];
                ldsm_x4(bw, s2u(Wb + b_ofs + nfp * 16 * HW + kk));
#pragma unroll
                for (int mf = 0; mf < 2; mf++) {
                    mma_f16(acc[mf][2 * nfp],     a[mf], bw[0], bw[1]);
                    mma_f16(acc[mf][2 * nfp + 1], a[mf], bw[2], bw[3]);
                }
            }
        }
        __syncthreads();
    }

#pragma unroll
    for (int mf = 0; mf < 2; mf++) {
#pragma unroll
        for (int hf = 0; hf < 2; hf++) {
            const int r = m0 + m0w + mf * 16 + hf * 8 + lr;
#pragma unroll
            for (int nf = 0; nf < 4; nf++) {
                const int c = n0 + n0w + nf * 8 + 2 * lc;
                *(float2*)&Y[(size_t)r * D + c] =
                    make_float2(acc[mf][nf][hf * 2] + bo[c],
                                acc[mf][nf][hf * 2 + 1] + bo[c + 1]);
            }
        }
    }
}

// ---------------------------------------------------------------------------
// Rel-pos flash attention (R13 structure): fragment softmax, ldmatrix loads,
// scale folded into Q fragments, 3 barriers per k-tile.
// ---------------------------------------------------------------------------
constexpr int HP  = 72;
constexpr int RST = 132;
constexpr int TILE_HB = 64 * HP * 2;    // 9216 bytes

constexpr int OFF_K  = 0;                        // 2 buffers
constexpr int OFF_VT = OFF_K  + 2 * TILE_HB;     // 2 buffers
constexpr int OFF_P  = OFF_VT + 2 * TILE_HB;     // 2 buffers
constexpr int OFF_PH = OFF_P  + 2 * TILE_HB;     // 64 x 72 half (Q stage / probs)
constexpr int OFF_BD = OFF_PH + TILE_HB;         // 64 x 132 half ring
constexpr int OFF_LS = OFF_BD + 64 * RST * 2;    // 128 floats
constexpr int ATT_BYTES = OFF_LS + 128 * 4;      // 82432 bytes

__global__ __launch_bounds__(256, 2)
void attn_fp16_kernel(const float* __restrict__ bu, const float* __restrict__ bvb) {
    extern __shared__ __align__(16) char smx[];
    __half* Ks  = (__half*)(smx + OFF_K);
    __half* Vts = (__half*)(smx + OFF_VT);
    __half* Ps  = (__half*)(smx + OFF_P);
    __half* Ph  = (__half*)(smx + OFF_PH);
    __half* BDh = (__half*)(smx + OFF_BD);
    float*  LS  = (float*) (smx + OFF_LS);

    const int tid = threadIdx.x;
    const int lane = tid & 31, wid = tid >> 5;
    const int wm = wid & 3, wn = wid >> 2;          // 4x2 warp grid
    const int m0w = wm * 16, n0w = wn * 32;         // warp tile 16x32
    const int lr = lane >> 2, lc = lane & 3;

    const int a_ofs = (m0w + (lane & 15)) * HP + ((lane >> 4) << 3);
    const int b_ofs = (n0w + (lane & 7) + ((lane >> 4) << 3)) * HP
                      + (((lane >> 3) & 1) << 3);

    const int q0 = blockIdx.x * 64;
    const int bh = blockIdx.y;
    const int b = bh >> 3, h = bh & 7;
    const int base_p = T - 1 - q0 - 63;   // >= 0

    const __half* qb = g_qh + (size_t)b * T * D + h * DK;
    const __half* kb = g_kh + (size_t)b * T * D + h * DK;
    const __half* vtb = g_vht + (size_t)bh * DK * T;
    const __half* pb = g_ph + h * DK;

    auto issue_kv = [&](int kt, int buf) {
        const __half* kbase = kb + (size_t)(kt * 64) * D;
        const __half* vbase = vtb + kt * 64;
        __half* Kd = Ks + buf * (64 * HP);
        __half* Vd = Vts + buf * (64 * HP);
#pragma unroll
        for (int it = 0; it < 2; it++) {
            int i = tid + it * 256;
            int r = i >> 3, c8 = (i & 7) * 8;
            cp16(s2u(&Kd[r * HP + c8]), kbase + (size_t)r * D + c8);
            cp16(s2u(&Vd[r * HP + c8]), vbase + (size_t)r * T + c8);
        }
    };
    auto issue_p = [&](int ch, int buf) {
        __half* Pd = Ps + buf * (64 * HP);
#pragma unroll
        for (int it = 0; it < 2; it++) {
            int i = tid + it * 256;
            int r = i >> 3, c8 = (i & 7) * 8;
            int g = base_p + ch * 64 + r;
            __half* dst = &Pd[r * HP + c8];
            if (g < L) cp16(s2u(dst), pb + (size_t)g * D + c8);
            else       *(float4*)dst = make_float4(0.f, 0.f, 0.f, 0.f);
        }
    };

    // ---- stage Q into Ph, build register A-fragments with bias+scale ----
#pragma unroll
    for (int it = 0; it < 2; it++) {
        int i = tid + it * 256;
        int r = i >> 3, c8 = (i & 7) * 8;
        cp16(s2u(&Ph[r * HP + c8]), qb + (size_t)(q0 + r) * D + c8);
    }
    cp_commit();
    cp_wait0();
    __syncthreads();

    constexpr float SCQ = 0.125f * 1.4426950408889634f;  // 1/sqrt(64) * log2(e)
    const int rA = m0w + lr, rB = rA + 8;
    uint32_t qf1[4][4], qf2[4][4];
#pragma unroll
    for (int ks = 0; ks < 4; ks++) {
        const int cc = ks * 16 + 2 * lc;
        float2 buL = *(const float2*)&bu[h * DK + cc];
        float2 buH = *(const float2*)&bu[h * DK + cc + 8];
        float2 bvL = *(const float2*)&bvb[h * DK + cc];
        float2 bvH = *(const float2*)&bvb[h * DK + cc + 8];
        float2 qaL = __half22float2(*(const __half2*)&Ph[rA * HP + cc]);
        float2 qbL = __half22float2(*(const __half2*)&Ph[rB * HP + cc]);
        float2 qaH = __half22float2(*(const __half2*)&Ph[rA * HP + cc + 8]);
        float2 qbH = __half22float2(*(const __half2*)&Ph[rB * HP + cc + 8]);
        qf1[ks][0] = h2u(__floats2half2_rn((qaL.x + buL.x) * SCQ, (qaL.y + buL.y) * SCQ));
        qf1[ks][1] = h2u(__floats2half2_rn((qbL.x + buL.x) * SCQ, (qbL.y + buL.y) * SCQ));
        qf1[ks][2] = h2u(__floats2half2_rn((qaH.x + buH.x) * SCQ, (qaH.y + buH.y) * SCQ));
        qf1[ks][3] = h2u(__floats2half2_rn((qbH.x + buH.x) * SCQ, (qbH.y + buH.y) * SCQ));
        qf2[ks][0] = h2u(__floats2half2_rn((qaL.x + bvL.x) * SCQ, (qaL.y + bvL.y) * SCQ));
        qf2[ks][1] = h2u(__floats2half2_rn((qbL.x + bvL.x) * SCQ, (qbL.y + bvL.y) * SCQ));
        qf2[ks][2] = h2u(__floats2half2_rn((qaH.x + bvH.x) * SCQ, (qaH.y + bvH.y) * SCQ));
        qf2[ks][3] = h2u(__floats2half2_rn((qbH.x + bvH.x) * SCQ, (qbH.y + bvH.y) * SCQ));
    }
    __syncthreads();   // Ph now free for probs

    issue_kv(0, 0);
    issue_p(0, 0);
    issue_p(1, 1);
    cp_commit();
    cp_wait0();
    __syncthreads();

    // ---- prologue: BD chunk 0 -> ring slot 0 ----
    {
        const __half* Pb = Ps;  // buf 0
        float accB[4][4] = {};
#pragma unroll
        for (int ks = 0; ks < 4; ks++) {
            const int kk = ks * 16;
#pragma unroll
            for (int nfp = 0; nfp < 2; nfp++) {
                uint32_t bp_[4];
                ldsm_x4(bp_, s2u(Pb + b_ofs + nfp * 16 * HP + kk));
                mma_f16(accB[2 * nfp],     qf2[ks], bp_[0], bp_[1]);
                mma_f16(accB[2 * nfp + 1], qf2[ks], bp_[2], bp_[3]);
            }
        }
#pragma unroll
        for (int nf = 0; nf < 4; nf++) {
            const int cr = n0w + nf * 8 + 2 * lc;
            uint32_t lo = h2u(__floats2half2_rn(accB[nf][0], accB[nf][1]));
            uint32_t hi = h2u(__floats2half2_rn(accB[nf][2], accB[nf][3]));
            *(uint32_t*)&BDh[rA * RST + cr] = lo;
            *(uint32_t*)&BDh[rB * RST + cr] = hi;
            if (cr < 4) {
                *(uint32_t*)&BDh[rA * RST + cr + 128] = lo;
                *(uint32_t*)&BDh[rB * RST + cr + 128] = hi;
            }
        }
    }
    __syncthreads();

    float O[4][4] = {};
    float lsumA = 0.f, lsumB = 0.f;

    for (int kt = 0; kt < 32; kt++) {
        if (kt + 1 < 32) issue_kv(kt + 1, (kt + 1) & 1);
        if (kt + 2 <= 32) issue_p(kt + 2, kt & 1);
        cp_commit();

        // --- (a) AC (regs) + BD chunk kt+1 (regs); write ring slot kt+1 ---
        const __half* Kb = Ks + (kt & 1) * (64 * HP);
        const __half* Pb = Ps + ((kt + 1) & 1) * (64 * HP);
        float accA[4][4] = {};
        {
            float accB[4][4] = {};
#pragma unroll
            for (int ks = 0; ks < 4; ks++) {
                const int kk = ks * 16;
#pragma unroll
                for (int nfp = 0; nfp < 2; nfp++) {
                    uint32_t bk_[4], bp_[4];
                    ldsm_x4(bk_, s2u(Kb + b_ofs + nfp * 16 * HP + kk));
                    mma_f16(accA[2 * nfp],     qf1[ks], bk_[0], bk_[1]);
                    mma_f16(accA[2 * nfp + 1], qf1[ks], bk_[2], bk_[3]);
                    ldsm_x4(bp_, s2u(Pb + b_ofs + nfp * 16 * HP + kk));
                    mma_f16(accB[2 * nfp],     qf2[ks], bp_[0], bp_[1]);
                    mma_f16(accB[2 * nfp + 1], qf2[ks], bp_[2], bp_[3]);
                }
            }
            const int slotc = ((kt + 1) & 1) * 64;
#pragma unroll
            for (int nf = 0; nf < 4; nf++) {
                const int cr = slotc + n0w + nf * 8 + 2 * lc;
                uint32_t lo = h2u(__floats2half2_rn(accB[nf][0], accB[nf][1]));
                uint32_t hi = h2u(__floats2half2_rn(accB[nf][2], accB[nf][3]));
                *(uint32_t*)&BDh[rA * RST + cr] = lo;
                *(uint32_t*)&BDh[rB * RST + cr] = hi;
                if (cr < 4) {
                    *(uint32_t*)&BDh[rA * RST + cr + 128] = lo;
                    *(uint32_t*)&BDh[rB * RST + cr + 128] = hi;
                }
            }
        }
        __syncthreads();   // ring complete: tile-kt window (both slots) valid

        // --- (b) fragment softmax on AC regs + ring reads -> probs in Ph ---
        {
            const int base_w = 63 + 64 * kt;
#pragma unroll
            for (int nf = 0; nf < 4; nf++) {
                const int c = n0w + nf * 8 + 2 * lc;
                const int wbA = (base_w - rA + c) & 127;
                const int wbB = (base_w - rB + c) & 127;
                float p0 = fast_exp2(accA[nf][0] + __half2float(BDh[rA * RST + wbA]));
                float p1 = fast_exp2(accA[nf][1] + __half2float(BDh[rA * RST + wbA + 1]));
                float p2 = fast_exp2(accA[nf][2] + __half2float(BDh[rB * RST + wbB]));
                float p3 = fast_exp2(accA[nf][3] + __half2float(BDh[rB * RST + wbB + 1]));
                lsumA += p0 + p1;
                lsumB += p2 + p3;
                *(uint32_t*)&Ph[rA * HP + c] = h2u(__floats2half2_rn(p0, p1));
                *(uint32_t*)&Ph[rB * HP + c] = h2u(__floats2half2_rn(p2, p3));
            }
        }
        __syncthreads();   // probs visible; ring slot-kt reads done

        // --- (c) P@V ---
        {
            const __half* Vb = Vts + (kt & 1) * (64 * HP);
#pragma unroll
            for (int ks = 0; ks < 4; ks++) {
                const int kk = ks * 16;
                uint32_t a[4];
                ldsm_x4(a, s2u(Ph + a_ofs + kk));
#pragma unroll
                for (int nfp = 0; nfp < 2; nfp++) {
                    uint32_t bv_[4];
                    ldsm_x4(bv_, s2u(Vb + b_ofs + nfp * 16 * HP + kk));
                    mma_f16(O[2 * nfp],     a, bv_[0], bv_[1]);
                    mma_f16(O[2 * nfp + 1], a, bv_[2], bv_[3]);
                }
            }
        }
        cp_wait0();
        __syncthreads();   // buffers ready, Ph free
    }

    // ---- final row-sum: quad shfl + 2-warp smem combine ----
    lsumA += __shfl_xor_sync(0xffffffffu, lsumA, 1);
    lsumA += __shfl_xor_sync(0xffffffffu, lsumA, 2);
    lsumB += __shfl_xor_sync(0xffffffffu, lsumB, 1);
    lsumB += __shfl_xor_sync(0xffffffffu, lsumB, 2);
    if (lc == 0) {
        LS[wn * 64 + rA] = lsumA;
        LS[wn * 64 + rB] = lsumB;
    }
    __syncthreads();

    {
        const float inv0 = 1.f / (LS[rA] + LS[64 + rA]);
        const float inv1 = 1.f / (LS[rB] + LS[64 + rB]);
        const size_t row0 = (size_t)(b * T + q0 + rA) * D + h * DK;
        const size_t row1 = row0 + (size_t)8 * D;
#pragma unroll
        for (int nf = 0; nf < 4; nf++) {
            const int c = n0w + nf * 8 + 2 * lc;
            *(__half2*)&g_aoh[row0 + c] =
                __floats2half2_rn(O[nf][0] * inv0, O[nf][1] * inv0);
            *(__half2*)&g_aoh[row1 + c] =
                __floats2half2_rn(O[nf][2] * inv1, O[nf][3] * inv1);
        }
    }
}

// ---------------------------------------------------------------------------
// Launch.  Inputs (metadata order):
//  0:q 1:k 2:v 3:p 4:mask(ignored) 5:Wq 6:bq 7:Wk 8:bk 9:Wv 10:bv
//  11:Wp 12:Wo 13:bo 14:bu 15:bv_bias
// ---------------------------------------------------------------------------
extern "C" void kernel_launch(void* const* d_in, const int* in_sizes, int n_in,
                              void* d_out, int out_size) {
    const float* q   = (const float*)d_in[0];
    const float* k   = (const float*)d_in[1];
    const float* v   = (const float*)d_in[2];
    const float* p   = (const float*)d_in[3];
    const float* Wq  = (const float*)d_in[5];
    const float* bq  = (const float*)d_in[6];
    const float* Wk  = (const float*)d_in[7];
    const float* bk  = (const float*)d_in[8];
    const float* Wv  = (const float*)d_in[9];
    const float* bv  = (const float*)d_in[10];
    const float* Wp  = (const float*)d_in[11];
    const float* Wo  = (const float*)d_in[12];
    const float* bo  = (const float*)d_in[13];
    const float* bu  = (const float*)d_in[14];
    const float* bvb = (const float*)d_in[15];
    float* out = (float*)d_out;

    cudaFuncSetAttribute(proj_fp16_kernel, cudaFuncAttributeMaxDynamicSharedMemorySize,
                         (int)PROJ_SMEM_BYTES);
    cudaFuncSetAttribute(out_gemm_fp16_kernel, cudaFuncAttributeMaxDynamicSharedMemorySize,
                         (int)OUT_SMEM_BYTES);
    cudaFuncSetAttribute(attn_fp16_kernel, cudaFuncAttributeMaxDynamicSharedMemorySize,
                         ATT_BYTES);

    const int M = B * T;  // 4096

    // Single fused fp32 -> fp16 conversion pass (9 segments)
    dim3 cvgrid(192, 9);
    f2h_all_kernel<<<cvgrid, 256>>>(
        (const float4*)q, (const float4*)k, (const float4*)v, (const float4*)p,
        (const float4*)Wq, (const float4*)Wk, (const float4*)Wv, (const float4*)Wp,
        (const float4*)Wo);

    dim3 blk(256);
    dim3 pjgrid(D / 128, (M + 127) / 128, 4);
    proj_fp16_kernel<<<pjgrid, blk, PROJ_SMEM_BYTES>>>(bq, bk, bv);

    dim3 agrid(T / 64, B * H);
    attn_fp16_kernel<<<agrid, 256, ATT_BYTES>>>(bu, bvb);

    dim3 ogrid(D / 64, M / 128, 1);   // 8 x 32 = 256 blocks
    out_gemm_fp16_kernel<<<ogrid, blk, OUT_SMEM_BYTES>>>(bo, out);
}